// round 1
// baseline (speedup 1.0000x reference)
#include <cuda_runtime.h>

#define DD 128
#define MAXN 40000
#define MAXE 600000

// Scratch (device globals: allocation-free rule)
__device__ float g_Ah[MAXN * DD];
__device__ float g_Bh[MAXN * DD];
__device__ float g_Dh[MAXN * DD];
__device__ float g_Eh[MAXN * DD];
__device__ float g_num[MAXN * DD];
__device__ float g_den[MAXN * DD];
__device__ int   g_deg[MAXN];

struct Smem {
    float Xs[16][132];   // transposed A tile (k-major), padded
    float Ws[16][128];   // B tile
};

__device__ __forceinline__ void red_add_v4(float* p, float4 v) {
    asm volatile("red.global.add.v4.f32 [%0], {%1,%2,%3,%4};"
                 :: "l"(p), "f"(v.x), "f"(v.y), "f"(v.z), "f"(v.w) : "memory");
}

// 128x128 output tile, K=128, BK=16, 256 threads, 8x8 per thread.
template<bool SCALE>
__device__ __forceinline__ void run_gemm(const float* __restrict__ X,
                                         const float* __restrict__ norm,
                                         const float* __restrict__ W,
                                         int M, int row0,
                                         Smem& sm, float acc[8][8])
{
    const int t = threadIdx.x;
    const int rowg = t >> 4, colg = t & 15;

    #pragma unroll
    for (int i = 0; i < 8; i++)
        #pragma unroll
        for (int j = 0; j < 8; j++) acc[i][j] = 0.f;

    for (int k0 = 0; k0 < DD; k0 += 16) {
        // Load X tile (128 rows x 16 cols), store transposed into Xs[k][row]
        #pragma unroll
        for (int i = 0; i < 2; i++) {
            int f = t + i * 256;           // float4 id in [0,512)
            int r = f >> 2;                // tile row
            int c4 = (f & 3) * 4;          // k offset within chunk
            int gr = row0 + r;
            float4 v = make_float4(0.f, 0.f, 0.f, 0.f);
            if (gr < M) {
                v = *(const float4*)(X + (size_t)gr * DD + k0 + c4);
                if (SCALE) {
                    float nm = __ldg(norm + gr);
                    v.x *= nm; v.y *= nm; v.z *= nm; v.w *= nm;
                }
            }
            sm.Xs[c4 + 0][r] = v.x;
            sm.Xs[c4 + 1][r] = v.y;
            sm.Xs[c4 + 2][r] = v.z;
            sm.Xs[c4 + 3][r] = v.w;
        }
        // Load W tile (16 rows x 128 cols), natural layout
        #pragma unroll
        for (int i = 0; i < 2; i++) {
            int f = t + i * 256;
            int kk = f >> 5;
            int c4 = (f & 31) * 4;
            *(float4*)&sm.Ws[kk][c4] = *(const float4*)(W + (size_t)(k0 + kk) * DD + c4);
        }
        __syncthreads();

        #pragma unroll
        for (int kk = 0; kk < 16; kk++) {
            float4 a0 = *(float4*)&sm.Xs[kk][rowg * 8];
            float4 a1 = *(float4*)&sm.Xs[kk][rowg * 8 + 4];
            float4 b0 = *(float4*)&sm.Ws[kk][colg * 8];
            float4 b1 = *(float4*)&sm.Ws[kk][colg * 8 + 4];
            float a[8] = {a0.x, a0.y, a0.z, a0.w, a1.x, a1.y, a1.z, a1.w};
            float b[8] = {b0.x, b0.y, b0.z, b0.w, b1.x, b1.y, b1.z, b1.w};
            #pragma unroll
            for (int i = 0; i < 8; i++)
                #pragma unroll
                for (int j = 0; j < 8; j++)
                    acc[i][j] += a[i] * b[j];
        }
        __syncthreads();
    }
}

__global__ void zero_kernel(int Nn) {
    int idx = blockIdx.x * blockDim.x + threadIdx.x;   // float4 index
    int total = Nn * (DD / 4);
    if (idx < total) {
        float4 z = make_float4(0.f, 0.f, 0.f, 0.f);
        ((float4*)g_num)[idx] = z;
        ((float4*)g_den)[idx] = z;
    }
    if (idx < Nn) g_deg[idx] = 0;
}

// blockIdx.y: 0->Ah(Wa), 1->Bh(Wb), 2->Dh(Wd), 3->Eh(We).  X = h * norm (fused).
__global__ __launch_bounds__(256, 2) void node_gemm_kernel(
    const float* __restrict__ h, const float* __restrict__ norm,
    const float* __restrict__ Wa, const float* __restrict__ ba,
    const float* __restrict__ Wb, const float* __restrict__ bb,
    const float* __restrict__ Wd, const float* __restrict__ bd,
    const float* __restrict__ We, const float* __restrict__ be,
    int M)
{
    __shared__ Smem sm;
    int y = blockIdx.y;
    const float* W    = (y == 0) ? Wa : (y == 1) ? Wb : (y == 2) ? Wd : We;
    const float* bias = (y == 0) ? ba : (y == 1) ? bb : (y == 2) ? bd : be;
    float* out        = (y == 0) ? g_Ah : (y == 1) ? g_Bh : (y == 2) ? g_Dh : g_Eh;

    int row0 = blockIdx.x * 128;
    float acc[8][8];
    run_gemm<true>(h, norm, W, M, row0, sm, acc);

    const int t = threadIdx.x;
    const int rowg = t >> 4, colg = t & 15;
    const int c0 = colg * 8;
    float4 bv0 = *(const float4*)(bias + c0);
    float4 bv1 = *(const float4*)(bias + c0 + 4);

    #pragma unroll
    for (int i = 0; i < 8; i++) {
        int r = row0 + rowg * 8 + i;
        if (r < M) {
            float4 v0 = make_float4(acc[i][0] + bv0.x, acc[i][1] + bv0.y,
                                    acc[i][2] + bv0.z, acc[i][3] + bv0.w);
            float4 v1 = make_float4(acc[i][4] + bv1.x, acc[i][5] + bv1.y,
                                    acc[i][6] + bv1.z, acc[i][7] + bv1.w);
            *(float4*)(out + (size_t)r * DD + c0)     = v0;
            *(float4*)(out + (size_t)r * DD + c0 + 4) = v1;
        }
    }
}

__device__ __forceinline__ float sigmoidf_fast(float x) {
    return 1.0f / (1.0f + __expf(-x));
}

// Ce = e @ Wc + bc, fused gate + scatter epilogue.
__global__ __launch_bounds__(256, 2) void edge_kernel(
    const float* __restrict__ e,
    const float* __restrict__ Wc, const float* __restrict__ bc,
    const int* __restrict__ src, const int* __restrict__ dst,
    float* __restrict__ eij_out, int M)
{
    __shared__ Smem sm;
    int row0 = blockIdx.x * 128;
    float acc[8][8];
    run_gemm<false>(e, nullptr, Wc, M, row0, sm, acc);

    const int t = threadIdx.x;
    const int rowg = t >> 4, colg = t & 15;
    const int c0 = colg * 8;
    float4 bv0 = *(const float4*)(bc + c0);
    float4 bv1 = *(const float4*)(bc + c0 + 4);

    #pragma unroll
    for (int i = 0; i < 8; i++) {
        int er = row0 + rowg * 8 + i;
        if (er >= M) break;
        int s = __ldg(src + er);
        int d = __ldg(dst + er);
        const float* Dhp = g_Dh + (size_t)s * DD + c0;
        const float* Ehp = g_Eh + (size_t)d * DD + c0;
        const float* Bhp = g_Bh + (size_t)s * DD + c0;
        float*       nup = g_num + (size_t)d * DD + c0;
        float*       dep = g_den + (size_t)d * DD + c0;

        float4 dh0 = *(const float4*)(Dhp);
        float4 dh1 = *(const float4*)(Dhp + 4);
        float4 eh0 = *(const float4*)(Ehp);
        float4 eh1 = *(const float4*)(Ehp + 4);
        float4 bh0 = *(const float4*)(Bhp);
        float4 bh1 = *(const float4*)(Bhp + 4);

        float4 x0 = make_float4(acc[i][0] + bv0.x + dh0.x + eh0.x,
                                acc[i][1] + bv0.y + dh0.y + eh0.y,
                                acc[i][2] + bv0.z + dh0.z + eh0.z,
                                acc[i][3] + bv0.w + dh0.w + eh0.w);
        float4 x1 = make_float4(acc[i][4] + bv1.x + dh1.x + eh1.x,
                                acc[i][5] + bv1.y + dh1.y + eh1.y,
                                acc[i][6] + bv1.z + dh1.z + eh1.z,
                                acc[i][7] + bv1.w + dh1.w + eh1.w);

        *(float4*)(eij_out + (size_t)er * DD + c0)     = x0;
        *(float4*)(eij_out + (size_t)er * DD + c0 + 4) = x1;

        float4 s0 = make_float4(sigmoidf_fast(x0.x), sigmoidf_fast(x0.y),
                                sigmoidf_fast(x0.z), sigmoidf_fast(x0.w));
        float4 s1 = make_float4(sigmoidf_fast(x1.x), sigmoidf_fast(x1.y),
                                sigmoidf_fast(x1.z), sigmoidf_fast(x1.w));

        float4 nb0 = make_float4(s0.x * bh0.x, s0.y * bh0.y, s0.z * bh0.z, s0.w * bh0.w);
        float4 nb1 = make_float4(s1.x * bh1.x, s1.y * bh1.y, s1.z * bh1.z, s1.w * bh1.w);

        red_add_v4(nup,     nb0);
        red_add_v4(nup + 4, nb1);
        red_add_v4(dep,     s0);
        red_add_v4(dep + 4, s1);

        if (colg == 0) atomicAdd(&g_deg[d], 1);
    }
}

__global__ void finalize_kernel(const float* __restrict__ h,
                                const float* __restrict__ norm,
                                float* __restrict__ out_h, int Nn)
{
    int idx = blockIdx.x * blockDim.x + threadIdx.x;   // float4 index
    int total = Nn * (DD / 4);
    if (idx >= total) return;
    int node = idx >> 5;
    float nm = __ldg(norm + node);
    float4 r;
    if (g_deg[node] > 0) {
        float4 a  = ((const float4*)g_Ah)[idx];
        float4 nu = ((const float4*)g_num)[idx];
        float4 de = ((const float4*)g_den)[idx];
        r.x = (a.x + nu.x / (de.x + 1e-6f)) * nm;
        r.y = (a.y + nu.y / (de.y + 1e-6f)) * nm;
        r.z = (a.z + nu.z / (de.z + 1e-6f)) * nm;
        r.w = (a.w + nu.w / (de.w + 1e-6f)) * nm;
    } else {
        float4 hh = *(const float4*)(h + (size_t)idx * 4);
        float sc = nm * nm;   // hs * norm = h * norm^2
        r = make_float4(hh.x * sc, hh.y * sc, hh.z * sc, hh.w * sc);
    }
    ((float4*)out_h)[idx] = r;
}

extern "C" void kernel_launch(void* const* d_in, const int* in_sizes, int n_in,
                              void* d_out, int out_size)
{
    const float* h    = (const float*)d_in[0];
    const float* e    = (const float*)d_in[1];
    const float* norm = (const float*)d_in[2];
    const int*   src  = (const int*)d_in[3];
    const int*   dst  = (const int*)d_in[4];
    const float* Wa = (const float*)d_in[5],  *ba = (const float*)d_in[6];
    const float* Wb = (const float*)d_in[7],  *bb = (const float*)d_in[8];
    const float* Wc = (const float*)d_in[9],  *bc = (const float*)d_in[10];
    const float* Wd = (const float*)d_in[11], *bd = (const float*)d_in[12];
    const float* We = (const float*)d_in[13], *be = (const float*)d_in[14];

    int Nn = in_sizes[0] / DD;   // 40000
    int Ee = in_sizes[3];        // 600000

    float* out_h = (float*)d_out;                        // [N, D]
    float* out_e = (float*)d_out + (size_t)Nn * DD;      // [E, D]

    int z_total = Nn * (DD / 4);
    zero_kernel<<<(z_total + 255) / 256, 256>>>(Nn);

    dim3 ngrid((Nn + 127) / 128, 4);
    node_gemm_kernel<<<ngrid, 256>>>(h, norm, Wa, ba, Wb, bb, Wd, bd, We, be, Nn);

    edge_kernel<<<(Ee + 127) / 128, 256>>>(e, Wc, bc, src, dst, out_e, Ee);

    finalize_kernel<<<(Nn * (DD / 4) + 255) / 256, 256>>>(h, norm, out_h, Nn);
}